// round 15
// baseline (speedup 1.0000x reference)
#include <cuda_runtime.h>
#include <cuda_fp16.h>
#include <cstdint>

#define N_NODES 4096
#define FEA 128
#define KD 4096
#define SPLITS 4
#define KSPL (KD / SPLITS)       // 1024
#define BK 64                    // k per tile (128B fp16 rows)
#define TILES (KSPL / BK)        // 16

// ---------------- device scratch (no allocations allowed) -------------------
__device__ __half g_b[(size_t)FEA * N_NODES];            // out1^T fp16 [f][node]
__device__ float g_part[SPLITS][(size_t)N_NODES * FEA];  // split-K partials
__device__ unsigned int g_cnt[32];                       // per-M-tile tickets

// ---------------- helpers ----------------------------------------------------
__device__ __forceinline__ uint32_t smem_u32(const void* p) {
    uint32_t a;
    asm("{ .reg .u64 t; cvta.to.shared.u64 t, %1; cvt.u32.u64 %0, t; }"
        : "=r"(a) : "l"(p));
    return a;
}
__device__ __forceinline__ void ldsm4(uint32_t* r, uint32_t addr) {
    asm volatile("ldmatrix.sync.aligned.m8n8.x4.shared.b16 {%0,%1,%2,%3}, [%4];"
                 : "=r"(r[0]), "=r"(r[1]), "=r"(r[2]), "=r"(r[3]) : "r"(addr));
}
__device__ __forceinline__ void mma16816(float* c, const uint32_t* a,
                                         const uint32_t* b) {
    asm volatile(
        "mma.sync.aligned.m16n8k16.row.col.f32.f16.f16.f32 "
        "{%0,%1,%2,%3}, {%4,%5,%6,%7}, {%8,%9}, {%0,%1,%2,%3};"
        : "+f"(c[0]), "+f"(c[1]), "+f"(c[2]), "+f"(c[3])
        : "r"(a[0]), "r"(a[1]), "r"(a[2]), "r"(a[3]), "r"(b[0]), "r"(b[1]));
}
__device__ __forceinline__ void cp16(uint32_t dst, const void* src) {
    asm volatile("cp.async.cg.shared.global [%0], [%1], 16;"
                 :: "r"(dst), "l"(src) : "memory");
}
__device__ __forceinline__ void cp_commit() {
    asm volatile("cp.async.commit_group;" ::: "memory");
}
__device__ __forceinline__ void cp_wait0() {
    asm volatile("cp.async.wait_group 0;" ::: "memory");
}

#define SWZ(o) ((uint32_t)(o) ^ ((((uint32_t)(o)) >> 3) & 0x70u))

__device__ __forceinline__ uint32_t h2_pack(__half a, __half b) {
    __half2 v; v.x = a; v.y = b;
    return *reinterpret_cast<uint32_t*>(&v);
}

// ---------------------------------------------------------------------------
// Kernel 1: per-node  support = x_n @ W_n, then out1_n = R_n @ support.
// (R10 body: no adj work here; 512 MB stream, ~84 us.)
// Emits out1 TRANSPOSED as a single fp16: B[f][node], K-major for the GEMM.
// ---------------------------------------------------------------------------
__global__ __launch_bounds__(128) void node_transform_kernel(
    const float* __restrict__ input,   // [N, 128]
    const float* __restrict__ rel,     // [N, 128, 128]
    const float* __restrict__ W)       // [N, 128, 128]
{
    const int n = blockIdx.x;
    const int t = threadIdx.x;

    __shared__ float in_row[FEA];
    __shared__ float s_vec[FEA];
    __shared__ float partf[4][FEA];

    in_row[t] = input[(size_t)n * FEA + t];
    __syncthreads();

    // ---- phase 1: support = x @ W, vectorized (LDG.128).
    {
        const int q = t & 31, g = t >> 5;
        const float* __restrict__ Wn = W + (size_t)n * FEA * FEA;
        float4 acc4 = make_float4(0.f, 0.f, 0.f, 0.f);
#pragma unroll 8
        for (int jj = 0; jj < 32; ++jj) {
            const int j = g * 32 + jj;
            const float4 w4 = *reinterpret_cast<const float4*>(
                &Wn[(size_t)j * FEA + 4 * q]);
            const float x = in_row[j];
            acc4.x += x * w4.x; acc4.y += x * w4.y;
            acc4.z += x * w4.z; acc4.w += x * w4.w;
        }
        *reinterpret_cast<float4*>(&partf[g][4 * q]) = acc4;
        __syncthreads();
        s_vec[t] = partf[0][t] + partf[1][t] + partf[2][t] + partf[3][t];
        __syncthreads();
    }

    // ---- phase 2: out1[j] = sum_k R[j,k] * s[k]
    const int w = t >> 5;
    const int l = t & 31;
    const float4 s4 = *reinterpret_cast<const float4*>(&s_vec[4 * l]);
    const float* __restrict__ Rn = rel + (size_t)n * FEA * FEA;

#pragma unroll 4
    for (int jj = 0; jj < 32; ++jj) {
        const int j = w * 32 + jj;
        const float4 r4 = *reinterpret_cast<const float4*>(&Rn[(size_t)j * FEA + 4 * l]);
        float p = r4.x * s4.x + r4.y * s4.y + r4.z * s4.z + r4.w * s4.w;
#pragma unroll
        for (int off = 16; off > 0; off >>= 1)
            p += __shfl_xor_sync(0xffffffffu, p, off);
        if (l == jj)
            g_b[(size_t)j * N_NODES + n] = __float2half_rn(p);
    }
}

// ---------------------------------------------------------------------------
// Kernel 2: split-K HMMA GEMM. A (fp32 adj) loaded 2 TILES AHEAD into regs,
// converted to fp16 one tile ahead (never waits on LDG); B fp16 via cp.async;
// fragment double-buffering; inline final reduction (last CTA per M-tile).
// CTA tile 128x128, BK=64, 16 warps (4M x 4N), 512 threads.
// ---------------------------------------------------------------------------
#define TILE_B 16384                        // one operand tile: 128 x 64 fp16
#define BUF_B (2 * TILE_B)                  // A, B
#define SMEM_REQ (2 * BUF_B + 1024)

__global__ __launch_bounds__(512, 1) void hmma_gemm_kernel(
    const float* __restrict__ A,
    const float* __restrict__ bias, float* __restrict__ out)
{
    extern __shared__ char dsm[];
    const uint32_t raw  = smem_u32(dsm);
    const uint32_t base = (raw + 1023u) & ~1023u;
    char* smb = dsm + (base - raw);

    const int t   = threadIdx.x;
    const int wid = t >> 5;
    const int l   = t & 31;
    const int m0  = blockIdx.x * 128;
    const int kb0 = blockIdx.y * KSPL;

    const int warpM = wid & 3;   // 0..3 -> 32 rows each
    const int warpN = wid >> 2;  // 0..3 -> 32 cols each

    // ---- per-lane ldmatrix address components ----
    uint32_t aRowOff[2], aXor[2];
#pragma unroll
    for (int mf = 0; mf < 2; ++mf) {
        const int r = warpM * 32 + mf * 16 + (l & 15);
        aRowOff[mf] = r * 128;
        aXor[mf]    = (r & 7) * 16;
    }
    const uint32_t aK = (l >> 4) * 16;
    uint32_t bRowOff[2], bXor[2];
#pragma unroll
    for (int q = 0; q < 2; ++q) {
        const int r = warpN * 32 + q * 16 + ((l >> 4) << 3) + (l & 7);
        bRowOff[q] = r * 128;
        bXor[q]    = (r & 7) * 16;
    }
    const uint32_t bK = ((l >> 3) & 1) * 16;

    // ---- staging maps (512 threads) ----
    const int aRow = t >> 2;                 // A: 128 rows, 4 threads/row
    const int aC4  = (t & 3) * 4;            // float4 idx, 4 per thread
    const int bRow = t >> 2;                 // B: 128 rows, 4 threads/row
    const int bC   = (t & 3) * 2;            // 16B chunk idx, 2 per thread

    float c[2][4][4];
#pragma unroll
    for (int i = 0; i < 2; ++i)
#pragma unroll
        for (int j = 0; j < 4; ++j)
#pragma unroll
            for (int k = 0; k < 4; ++k) c[i][j][k] = 0.0f;

    float4 aReg[2][4];   // two in-flight A tiles (tile kt+1, tile kt+2)

    auto ldgA = [&](float4* dst, int kb) {
#pragma unroll
        for (int r = 0; r < 4; ++r)
            dst[r] = *reinterpret_cast<const float4*>(
                &A[(size_t)(m0 + aRow) * KD + kb + ((aC4 + r) << 2)]);
    };

    auto stageB = [&](uint32_t dstBuf, int kb) {
#pragma unroll
        for (int r = 0; r < 2; ++r) {
            const uint32_t dof = SWZ(bRow * 128 + (bC + r) * 16);
            cp16(base + dstBuf + TILE_B + dof,
                 &g_b[(size_t)bRow * KD + kb + (bC + r) * 8]);
        }
        cp_commit();
    };

    auto convert_store = [&](const float4* src, uint32_t dstBuf) {
#pragma unroll
        for (int r = 0; r < 4; ++r) {
            const float4 v = src[r];
            uint2 hv;
            hv.x = h2_pack(__float2half_rn(v.x), __float2half_rn(v.y));
            hv.y = h2_pack(__float2half_rn(v.z), __float2half_rn(v.w));
            const uint32_t off = SWZ(aRow * 128 + (aC4 + r) * 8);
            *reinterpret_cast<uint2*>(smb + dstBuf + off) = hv;
        }
    };

    auto load_frags = [&](uint32_t cur, int st, uint32_t fa[2][4],
                          uint32_t fb[2][4]) {
        const uint32_t aB = base + cur;
        const uint32_t bB = aB + TILE_B;
        const uint32_t k2 = st * 32;
#pragma unroll
        for (int mf = 0; mf < 2; ++mf)
            ldsm4(fa[mf], aB + aRowOff[mf] + ((aK + k2) ^ aXor[mf]));
#pragma unroll
        for (int q = 0; q < 2; ++q)
            ldsm4(fb[q], bB + bRowOff[q] + ((bK + k2) ^ bXor[q]));
    };

    auto do_mma = [&](uint32_t fa[2][4], uint32_t fb[2][4]) {
#pragma unroll
        for (int mf = 0; mf < 2; ++mf)
#pragma unroll
            for (int q = 0; q < 2; ++q)
#pragma unroll
                for (int h = 0; h < 2; ++h)
                    mma16816(c[mf][2 * q + h], fa[mf], &fb[q][2 * h]);
    };

    // ================== prologue =================
    // aReg[0] <- tile 0; convert to buf0; aReg[1] <- tile 1; B tile0 -> buf0.
    ldgA(aReg[0], kb0);
    stageB(0, kb0);
    convert_store(aReg[0], 0);       // the only convert that waits on its LDG
    ldgA(aReg[1], kb0 + BK);
    cp_wait0();
    __syncthreads();

    uint32_t fa[2][2][4], fb[2][2][4];

    // ================== main loop ==============================
    // invariant at top of iter kt: buffer cur holds tile kt (A+B);
    // aReg[(kt+1)&1] holds A-tile kt+1 (loaded >= 1 iter ago).
    for (int kt = 0; kt < TILES; ++kt) {
        const uint32_t cur = (kt & 1) * BUF_B;
        const uint32_t nxt = cur ^ BUF_B;
        const bool have1 = (kt + 1) < TILES;
        const bool have2 = (kt + 2) < TILES;

        if (have1) stageB(nxt, kb0 + (kt + 1) * BK);
        if (have2) ldgA(aReg[kt & 1], kb0 + (kt + 2) * BK);  // fire early

        load_frags(cur, 0, fa[0], fb[0]);
        // steps 0-1
#pragma unroll
        for (int st = 0; st < 2; ++st) {
            load_frags(cur, st + 1, fa[(st + 1) & 1], fb[(st + 1) & 1]);
            do_mma(fa[st & 1], fb[st & 1]);
        }
        // convert tile kt+1 (data long since arrived) between MMA halves
        if (have1) convert_store(aReg[(kt + 1) & 1], nxt);
        // steps 2-3
#pragma unroll
        for (int st = 2; st < 4; ++st) {
            if (st < 3) load_frags(cur, st + 1, fa[(st + 1) & 1], fb[(st + 1) & 1]);
            do_mma(fa[st & 1], fb[st & 1]);
        }

        if (have1) {
            cp_wait0();
            __syncthreads();
        }
    }

    // ---- store this split's partial (coalesced) ----
    float* __restrict__ part = g_part[blockIdx.y];
    const int cRow = (l >> 2);
    const int cCol = (l & 3) * 2;
#pragma unroll
    for (int mf = 0; mf < 2; ++mf) {
        const int rbase = m0 + warpM * 32 + mf * 16 + cRow;
#pragma unroll
        for (int nf = 0; nf < 4; ++nf) {
            const int col = warpN * 32 + nf * 8 + cCol;
            float2 v0; v0.x = c[mf][nf][0]; v0.y = c[mf][nf][1];
            float2 v1; v1.x = c[mf][nf][2]; v1.y = c[mf][nf][3];
            *reinterpret_cast<float2*>(&part[(size_t)rbase * FEA + col])       = v0;
            *reinterpret_cast<float2*>(&part[(size_t)(rbase + 8) * FEA + col]) = v1;
        }
    }

    // ---- inline reduction: last CTA per M-tile sums partials + bias ----
    __threadfence();
    __shared__ unsigned int tick;
    if (t == 0) tick = atomicAdd(&g_cnt[blockIdx.x], 1u);
    __syncthreads();
    if (tick == SPLITS - 1) {
        const float4* __restrict__ b4 = reinterpret_cast<const float4*>(bias);
        float4* __restrict__ o4 = reinterpret_cast<float4*>(out);
        for (int i = t; i < 128 * (FEA / 4); i += 512) {
            const int row = m0 + (i >> 5);
            const int c4  = i & 31;
            const size_t idx = (size_t)row * (FEA / 4) + c4;
            float4 o = b4[c4];
#pragma unroll
            for (int s = 0; s < SPLITS; ++s) {
                const float4 p = reinterpret_cast<const float4*>(g_part[s])[idx];
                o.x += p.x; o.y += p.y; o.z += p.z; o.w += p.w;
            }
            o4[idx] = o;
        }
        if (t == 0) g_cnt[blockIdx.x] = 0;   // reset for graph replay
    }
}

extern "C" void kernel_launch(void* const* d_in, const int* in_sizes, int n_in,
                              void* d_out, int out_size)
{
    const float* input = (const float*)d_in[0];  // [4096, 128]
    const float* adj   = (const float*)d_in[1];  // [4096, 4096]
    const float* rel   = (const float*)d_in[2];  // [4096, 128, 128]
    const float* W     = (const float*)d_in[3];  // [4096, 128, 128]
    const float* bias  = (const float*)d_in[4];  // [128]
    float* out = (float*)d_out;                  // [4096, 128]

    cudaFuncSetAttribute(hmma_gemm_kernel,
                         cudaFuncAttributeMaxDynamicSharedMemorySize, SMEM_REQ);

    node_transform_kernel<<<N_NODES, 128>>>(input, rel, W);
    hmma_gemm_kernel<<<dim3(32, SPLITS), 512, SMEM_REQ>>>(adj, bias, out);
}

// round 16
// speedup vs baseline: 1.1539x; 1.1539x over previous
#include <cuda_runtime.h>
#include <cuda_fp16.h>
#include <cstdint>

#define N_NODES 4096
#define FEA 128
#define KD 4096
#define SPLITS 4
#define KSPL (KD / SPLITS)       // 1024
#define BK 64                    // k per tile
#define TILES (KSPL / BK)        // 16

// ---------------- device scratch (no allocations allowed) -------------------
__device__ __half g_b[(size_t)FEA * N_NODES];            // out1^T fp16 [f][node]
__device__ float g_part[SPLITS][(size_t)N_NODES * FEA];  // split-K partials
__device__ unsigned int g_cnt[32];                       // per-M-tile tickets

// ---------------- helpers ----------------------------------------------------
__device__ __forceinline__ uint32_t smem_u32(const void* p) {
    uint32_t a;
    asm("{ .reg .u64 t; cvta.to.shared.u64 t, %1; cvt.u32.u64 %0, t; }"
        : "=r"(a) : "l"(p));
    return a;
}
__device__ __forceinline__ void ldsm4(uint32_t* r, uint32_t addr) {
    asm volatile("ldmatrix.sync.aligned.m8n8.x4.shared.b16 {%0,%1,%2,%3}, [%4];"
                 : "=r"(r[0]), "=r"(r[1]), "=r"(r[2]), "=r"(r[3]) : "r"(addr));
}
__device__ __forceinline__ void mma16816(float* c, const uint32_t* a,
                                         const uint32_t* b) {
    asm volatile(
        "mma.sync.aligned.m16n8k16.row.col.f32.f16.f16.f32 "
        "{%0,%1,%2,%3}, {%4,%5,%6,%7}, {%8,%9}, {%0,%1,%2,%3};"
        : "+f"(c[0]), "+f"(c[1]), "+f"(c[2]), "+f"(c[3])
        : "r"(a[0]), "r"(a[1]), "r"(a[2]), "r"(a[3]), "r"(b[0]), "r"(b[1]));
}
__device__ __forceinline__ void cp16(uint32_t dst, const void* src) {
    asm volatile("cp.async.cg.shared.global [%0], [%1], 16;"
                 :: "r"(dst), "l"(src) : "memory");
}
__device__ __forceinline__ void cp_commit() {
    asm volatile("cp.async.commit_group;" ::: "memory");
}
__device__ __forceinline__ void cp_wait0() {
    asm volatile("cp.async.wait_group 0;" ::: "memory");
}

#define SWZ(o) ((uint32_t)(o) ^ ((((uint32_t)(o)) >> 3) & 0x70u))

__device__ __forceinline__ uint32_t h2_pack(__half a, __half b) {
    __half2 v; v.x = a; v.y = b;
    return *reinterpret_cast<uint32_t*>(&v);
}

// ---------------------------------------------------------------------------
// Kernel 1: per-node  support = x_n @ W_n, then out1_n = R_n @ support.
// (Proven R10 body, ~84 us at 82% DRAM.)
// ---------------------------------------------------------------------------
__global__ __launch_bounds__(128) void node_transform_kernel(
    const float* __restrict__ input,   // [N, 128]
    const float* __restrict__ rel,     // [N, 128, 128]
    const float* __restrict__ W)       // [N, 128, 128]
{
    const int n = blockIdx.x;
    const int t = threadIdx.x;

    __shared__ float in_row[FEA];
    __shared__ float s_vec[FEA];
    __shared__ float partf[4][FEA];

    in_row[t] = input[(size_t)n * FEA + t];
    __syncthreads();

    {
        const int q = t & 31, g = t >> 5;
        const float* __restrict__ Wn = W + (size_t)n * FEA * FEA;
        float4 acc4 = make_float4(0.f, 0.f, 0.f, 0.f);
#pragma unroll 8
        for (int jj = 0; jj < 32; ++jj) {
            const int j = g * 32 + jj;
            const float4 w4 = *reinterpret_cast<const float4*>(
                &Wn[(size_t)j * FEA + 4 * q]);
            const float x = in_row[j];
            acc4.x += x * w4.x; acc4.y += x * w4.y;
            acc4.z += x * w4.z; acc4.w += x * w4.w;
        }
        *reinterpret_cast<float4*>(&partf[g][4 * q]) = acc4;
        __syncthreads();
        s_vec[t] = partf[0][t] + partf[1][t] + partf[2][t] + partf[3][t];
        __syncthreads();
    }

    const int w = t >> 5;
    const int l = t & 31;
    const float4 s4 = *reinterpret_cast<const float4*>(&s_vec[4 * l]);
    const float* __restrict__ Rn = rel + (size_t)n * FEA * FEA;

#pragma unroll 4
    for (int jj = 0; jj < 32; ++jj) {
        const int j = w * 32 + jj;
        const float4 r4 = *reinterpret_cast<const float4*>(&Rn[(size_t)j * FEA + 4 * l]);
        float p = r4.x * s4.x + r4.y * s4.y + r4.z * s4.z + r4.w * s4.w;
#pragma unroll
        for (int off = 16; off > 0; off >>= 1)
            p += __shfl_xor_sync(0xffffffffu, p, off);
        if (l == jj)
            g_b[(size_t)j * N_NODES + n] = __float2half_rn(p);
    }
}

// ---------------------------------------------------------------------------
// Kernel 2: split-K HMMA GEMM. A staged as FP32 via cp.async (deep pipeline
// hides DRAM latency), converted fp32->fp16 in SMEM behind the double buffer.
// B fp16 via cp.async. Fragment double-buffering. Inline ticket reduction.
// CTA tile 128x128, BK=64, 16 warps (4M x 4N), 512 threads.
// smem: A16[2]x16KB @0, B16[2]x16KB @32K, A32[2]x40KB @64K (320B rows).
// ---------------------------------------------------------------------------
#define A16_OFF 0
#define B16_OFF 32768
#define A32_OFF 65536
#define A16_BUF 16384
#define B16_BUF 16384
#define A32_BUF 40960
#define A32_STRIDE 320
#define SMEM_REQ (A32_OFF + 2 * A32_BUF + 1024)

__global__ __launch_bounds__(512, 1) void hmma_gemm_kernel(
    const float* __restrict__ A,
    const float* __restrict__ bias, float* __restrict__ out)
{
    extern __shared__ char dsm[];
    const uint32_t raw  = smem_u32(dsm);
    const uint32_t base = (raw + 1023u) & ~1023u;

    const int t   = threadIdx.x;
    const int wid = t >> 5;
    const int l   = t & 31;
    const int m0  = blockIdx.x * 128;
    const int kb0 = blockIdx.y * KSPL;

    const int warpM = wid & 3;   // 0..3 -> 32 rows each
    const int warpN = wid >> 2;  // 0..3 -> 32 cols each

    // ---- per-lane ldmatrix address components ----
    uint32_t aRowOff[2], aXor[2];
#pragma unroll
    for (int mf = 0; mf < 2; ++mf) {
        const int r = warpM * 32 + mf * 16 + (l & 15);
        aRowOff[mf] = r * 128;
        aXor[mf]    = (r & 7) * 16;
    }
    const uint32_t aK = (l >> 4) * 16;
    uint32_t bRowOff[2], bXor[2];
#pragma unroll
    for (int q = 0; q < 2; ++q) {
        const int r = warpN * 32 + q * 16 + ((l >> 4) << 3) + (l & 7);
        bRowOff[q] = r * 128;
        bXor[q]    = (r & 7) * 16;
    }
    const uint32_t bK = ((l >> 3) & 1) * 16;

    // ---- staging maps (512 threads) ----
    const int aRow = t >> 2;                 // 128 rows, 4 threads/row
    const int bC   = (t & 3) * 2;            // B: 16B chunk idx, 2 per thread

    float c[2][4][4];
#pragma unroll
    for (int i = 0; i < 2; ++i)
#pragma unroll
        for (int j = 0; j < 4; ++j)
#pragma unroll
            for (int k = 0; k < 4; ++k) c[i][j][k] = 0.0f;

    // stage A32 + B16 tile into buffer `buf`
    auto stage = [&](int buf, int kb) {
#pragma unroll
        for (int r = 0; r < 2; ++r) {
            const uint32_t dof = SWZ(aRow * 128 + (bC + r) * 16);
            cp16(base + B16_OFF + buf * B16_BUF + dof,
                 &g_b[(size_t)aRow * KD + kb + (bC + r) * 8]);
        }
#pragma unroll
        for (int r = 0; r < 4; ++r) {
            const int c16 = (t & 3) + 4 * r;   // stride-4 interleave (bank map)
            cp16(base + A32_OFF + buf * A32_BUF + aRow * A32_STRIDE + c16 * 16,
                 &A[(size_t)(m0 + aRow) * KD + kb + c16 * 4]);
        }
        cp_commit();
    };

    // convert A32[buf] -> A16[buf] (smem -> smem, conflict-engineered)
    auto convertA = [&](int buf) {
        const uint32_t src = base + A32_OFF + buf * A32_BUF + aRow * A32_STRIDE;
        const uint32_t dst = base + A16_OFF + buf * A16_BUF;
#pragma unroll
        for (int r = 0; r < 4; ++r) {
            const int c16 = (t & 3) + 4 * r;
            float x, y, z, w;
            asm volatile("ld.shared.v4.f32 {%0,%1,%2,%3}, [%4];"
                         : "=f"(x), "=f"(y), "=f"(z), "=f"(w)
                         : "r"(src + c16 * 16));
            const uint32_t h0 = h2_pack(__float2half_rn(x), __float2half_rn(y));
            const uint32_t h1 = h2_pack(__float2half_rn(z), __float2half_rn(w));
            asm volatile("st.shared.v2.u32 [%0], {%1,%2};"
                         :: "r"(dst + SWZ(aRow * 128 + c16 * 8)), "r"(h0), "r"(h1));
        }
    };

    auto load_frags = [&](int cur, int st, uint32_t fa[2][4], uint32_t fb[2][4]) {
        const uint32_t aB = base + A16_OFF + cur * A16_BUF;
        const uint32_t bB = base + B16_OFF + cur * B16_BUF;
        const uint32_t k2 = st * 32;
#pragma unroll
        for (int mf = 0; mf < 2; ++mf)
            ldsm4(fa[mf], aB + aRowOff[mf] + ((aK + k2) ^ aXor[mf]));
#pragma unroll
        for (int q = 0; q < 2; ++q)
            ldsm4(fb[q], bB + bRowOff[q] + ((bK + k2) ^ bXor[q]));
    };

    auto do_mma = [&](uint32_t fa[2][4], uint32_t fb[2][4]) {
#pragma unroll
        for (int mf = 0; mf < 2; ++mf)
#pragma unroll
            for (int q = 0; q < 2; ++q)
#pragma unroll
                for (int h = 0; h < 2; ++h)
                    mma16816(c[mf][2 * q + h], fa[mf], &fb[q][2 * h]);
    };

    // ================== prologue: tile 0 =================
    stage(0, kb0);
    cp_wait0();
    __syncthreads();
    convertA(0);
    __syncthreads();

    uint32_t fa[2][2][4], fb[2][2][4];

    // ================== main loop ==============================
    for (int kt = 0; kt < TILES; ++kt) {
        const int cur = kt & 1;
        const int nxt = cur ^ 1;
        const bool have_next = (kt + 1) < TILES;

        if (have_next) stage(nxt, kb0 + (kt + 1) * BK);

        load_frags(cur, 0, fa[0], fb[0]);
#pragma unroll
        for (int st = 0; st < 4; ++st) {
            if (st < 3) load_frags(cur, st + 1, fa[(st + 1) & 1], fb[(st + 1) & 1]);
            do_mma(fa[st & 1], fb[st & 1]);
        }

        if (have_next) {
            cp_wait0();          // A32/B16 for tile kt+1 have landed
            __syncthreads();
            convertA(nxt);       // short smem->smem burst, off DRAM path
            __syncthreads();
        }
    }

    // ---- store this split's partial (coalesced) ----
    float* __restrict__ part = g_part[blockIdx.y];
    const int cRow = (l >> 2);
    const int cCol = (l & 3) * 2;
#pragma unroll
    for (int mf = 0; mf < 2; ++mf) {
        const int rbase = m0 + warpM * 32 + mf * 16 + cRow;
#pragma unroll
        for (int nf = 0; nf < 4; ++nf) {
            const int col = warpN * 32 + nf * 8 + cCol;
            float2 v0; v0.x = c[mf][nf][0]; v0.y = c[mf][nf][1];
            float2 v1; v1.x = c[mf][nf][2]; v1.y = c[mf][nf][3];
            *reinterpret_cast<float2*>(&part[(size_t)rbase * FEA + col])       = v0;
            *reinterpret_cast<float2*>(&part[(size_t)(rbase + 8) * FEA + col]) = v1;
        }
    }

    // ---- inline reduction: last CTA per M-tile sums partials + bias ----
    __threadfence();
    __shared__ unsigned int tick;
    if (t == 0) tick = atomicAdd(&g_cnt[blockIdx.x], 1u);
    __syncthreads();
    if (tick == SPLITS - 1) {
        const float4* __restrict__ b4 = reinterpret_cast<const float4*>(bias);
        float4* __restrict__ o4 = reinterpret_cast<float4*>(out);
        for (int i = t; i < 128 * (FEA / 4); i += 512) {
            const int row = m0 + (i >> 5);
            const int c4  = i & 31;
            const size_t idx = (size_t)row * (FEA / 4) + c4;
            float4 o = b4[c4];
#pragma unroll
            for (int s = 0; s < SPLITS; ++s) {
                const float4 p = reinterpret_cast<const float4*>(g_part[s])[idx];
                o.x += p.x; o.y += p.y; o.z += p.z; o.w += p.w;
            }
            o4[idx] = o;
        }
        if (t == 0) g_cnt[blockIdx.x] = 0;   // reset for graph replay
    }
}

extern "C" void kernel_launch(void* const* d_in, const int* in_sizes, int n_in,
                              void* d_out, int out_size)
{
    const float* input = (const float*)d_in[0];  // [4096, 128]
    const float* adj   = (const float*)d_in[1];  // [4096, 4096]
    const float* rel   = (const float*)d_in[2];  // [4096, 128, 128]
    const float* W     = (const float*)d_in[3];  // [4096, 128, 128]
    const float* bias  = (const float*)d_in[4];  // [128]
    float* out = (float*)d_out;                  // [4096, 128]

    cudaFuncSetAttribute(hmma_gemm_kernel,
                         cudaFuncAttributeMaxDynamicSharedMemorySize, SMEM_REQ);

    node_transform_kernel<<<N_NODES, 128>>>(input, rel, W);
    hmma_gemm_kernel<<<dim3(32, SPLITS), 512, SMEM_REQ>>>(adj, bias, out);
}

// round 17
// speedup vs baseline: 1.1967x; 1.0371x over previous
#include <cuda_runtime.h>
#include <cuda_fp16.h>
#include <cstdint>

#define N_NODES 4096
#define FEA 128
#define KD 4096
#define SPLITS 4
#define KSPL (KD / SPLITS)       // 1024
#define BK 64                    // k per tile
#define TILES (KSPL / BK)        // 16

// ---------------- device scratch (no allocations allowed) -------------------
__device__ __half g_b[(size_t)FEA * N_NODES];            // out1^T fp16 [f][node]
__device__ float g_part[SPLITS][(size_t)N_NODES * FEA];  // split-K partials
__device__ unsigned int g_cnt[32];                       // per-M-tile tickets

// ---------------- helpers ----------------------------------------------------
__device__ __forceinline__ uint32_t smem_u32(const void* p) {
    uint32_t a;
    asm("{ .reg .u64 t; cvta.to.shared.u64 t, %1; cvt.u32.u64 %0, t; }"
        : "=r"(a) : "l"(p));
    return a;
}
__device__ __forceinline__ void ldsm4(uint32_t* r, uint32_t addr) {
    asm volatile("ldmatrix.sync.aligned.m8n8.x4.shared.b16 {%0,%1,%2,%3}, [%4];"
                 : "=r"(r[0]), "=r"(r[1]), "=r"(r[2]), "=r"(r[3]) : "r"(addr));
}
__device__ __forceinline__ void mma16816(float* c, const uint32_t* a,
                                         const uint32_t* b) {
    asm volatile(
        "mma.sync.aligned.m16n8k16.row.col.f32.f16.f16.f32 "
        "{%0,%1,%2,%3}, {%4,%5,%6,%7}, {%8,%9}, {%0,%1,%2,%3};"
        : "+f"(c[0]), "+f"(c[1]), "+f"(c[2]), "+f"(c[3])
        : "r"(a[0]), "r"(a[1]), "r"(a[2]), "r"(a[3]), "r"(b[0]), "r"(b[1]));
}
__device__ __forceinline__ void cp16(uint32_t dst, const void* src) {
    asm volatile("cp.async.cg.shared.global [%0], [%1], 16;"
                 :: "r"(dst), "l"(src) : "memory");
}
__device__ __forceinline__ void cp_commit() {
    asm volatile("cp.async.commit_group;" ::: "memory");
}
template <int N>
__device__ __forceinline__ void cp_waitg() {
    asm volatile("cp.async.wait_group %0;" :: "n"(N) : "memory");
}

#define SWZ(o) ((uint32_t)(o) ^ ((((uint32_t)(o)) >> 3) & 0x70u))

__device__ __forceinline__ uint32_t h2_pack(__half a, __half b) {
    __half2 v; v.x = a; v.y = b;
    return *reinterpret_cast<uint32_t*>(&v);
}

// ---------------------------------------------------------------------------
// Kernel 1: per-node  support = x_n @ W_n, then out1_n = R_n @ support.
// (Proven R10 body, ~84 us at 82% DRAM.)
// ---------------------------------------------------------------------------
__global__ __launch_bounds__(128) void node_transform_kernel(
    const float* __restrict__ input,   // [N, 128]
    const float* __restrict__ rel,     // [N, 128, 128]
    const float* __restrict__ W)       // [N, 128, 128]
{
    const int n = blockIdx.x;
    const int t = threadIdx.x;

    __shared__ float in_row[FEA];
    __shared__ float s_vec[FEA];
    __shared__ float partf[4][FEA];

    in_row[t] = input[(size_t)n * FEA + t];
    __syncthreads();

    {
        const int q = t & 31, g = t >> 5;
        const float* __restrict__ Wn = W + (size_t)n * FEA * FEA;
        float4 acc4 = make_float4(0.f, 0.f, 0.f, 0.f);
#pragma unroll 8
        for (int jj = 0; jj < 32; ++jj) {
            const int j = g * 32 + jj;
            const float4 w4 = *reinterpret_cast<const float4*>(
                &Wn[(size_t)j * FEA + 4 * q]);
            const float x = in_row[j];
            acc4.x += x * w4.x; acc4.y += x * w4.y;
            acc4.z += x * w4.z; acc4.w += x * w4.w;
        }
        *reinterpret_cast<float4*>(&partf[g][4 * q]) = acc4;
        __syncthreads();
        s_vec[t] = partf[0][t] + partf[1][t] + partf[2][t] + partf[3][t];
        __syncthreads();
    }

    const int w = t >> 5;
    const int l = t & 31;
    const float4 s4 = *reinterpret_cast<const float4*>(&s_vec[4 * l]);
    const float* __restrict__ Rn = rel + (size_t)n * FEA * FEA;

#pragma unroll 4
    for (int jj = 0; jj < 32; ++jj) {
        const int j = w * 32 + jj;
        const float4 r4 = *reinterpret_cast<const float4*>(&Rn[(size_t)j * FEA + 4 * l]);
        float p = r4.x * s4.x + r4.y * s4.y + r4.z * s4.z + r4.w * s4.w;
#pragma unroll
        for (int off = 16; off > 0; off >>= 1)
            p += __shfl_xor_sync(0xffffffffu, p, off);
        if (l == jj)
            g_b[(size_t)j * N_NODES + n] = __float2half_rn(p);
    }
}

// ---------------------------------------------------------------------------
// Kernel 2: split-K HMMA GEMM, TRIPLE-buffered (2 tiles of DRAM lookahead).
// A staged fp32 via cp.async, converted fp32->fp16 in SMEM (each thread
// converts its own staged bytes -> no barrier between wait and convert);
// ONE __syncthreads per tile. Fragment double-buffering. Inline reduction.
// CTA tile 128x128, BK=64, 16 warps (4M x 4N), 512 threads.
// smem: A16[3]x16KB @0, B16[3]x16KB @48K, A32[3]x40KB @96K  (216KB+pad)
// ---------------------------------------------------------------------------
#define A16_OFF 0
#define B16_OFF 49152
#define A32_OFF 98304
#define A16_BUF 16384
#define B16_BUF 16384
#define A32_BUF 40960
#define A32_STRIDE 320
#define SMEM_REQ (A32_OFF + 3 * A32_BUF + 1024)   // 222208

__global__ __launch_bounds__(512, 1) void hmma_gemm_kernel(
    const float* __restrict__ A,
    const float* __restrict__ bias, float* __restrict__ out)
{
    extern __shared__ char dsm[];
    const uint32_t raw  = smem_u32(dsm);
    const uint32_t base = (raw + 1023u) & ~1023u;

    const int t   = threadIdx.x;
    const int wid = t >> 5;
    const int l   = t & 31;
    const int m0  = blockIdx.x * 128;
    const int kb0 = blockIdx.y * KSPL;

    const int warpM = wid & 3;   // 0..3 -> 32 rows each
    const int warpN = wid >> 2;  // 0..3 -> 32 cols each

    // ---- per-lane ldmatrix address components ----
    uint32_t aRowOff[2], aXor[2];
#pragma unroll
    for (int mf = 0; mf < 2; ++mf) {
        const int r = warpM * 32 + mf * 16 + (l & 15);
        aRowOff[mf] = r * 128;
        aXor[mf]    = (r & 7) * 16;
    }
    const uint32_t aK = (l >> 4) * 16;
    uint32_t bRowOff[2], bXor[2];
#pragma unroll
    for (int q = 0; q < 2; ++q) {
        const int r = warpN * 32 + q * 16 + ((l >> 4) << 3) + (l & 7);
        bRowOff[q] = r * 128;
        bXor[q]    = (r & 7) * 16;
    }
    const uint32_t bK = ((l >> 3) & 1) * 16;

    // ---- staging maps (512 threads) ----
    const int aRow = t >> 2;                 // 128 rows, 4 threads/row
    const int bC   = (t & 3) * 2;            // B: 16B chunk idx, 2 per thread

    float c[2][4][4];
#pragma unroll
    for (int i = 0; i < 2; ++i)
#pragma unroll
        for (int j = 0; j < 4; ++j)
#pragma unroll
            for (int k = 0; k < 4; ++k) c[i][j][k] = 0.0f;

    // stage A32 + B16 for tile index kt into buffer buf; one commit group
    auto stage = [&](int buf, int kt) {
        const int kb = kb0 + kt * BK;
#pragma unroll
        for (int r = 0; r < 2; ++r) {
            const uint32_t dof = SWZ(aRow * 128 + (bC + r) * 16);
            cp16(base + B16_OFF + buf * B16_BUF + dof,
                 &g_b[(size_t)aRow * KD + kb + (bC + r) * 8]);
        }
#pragma unroll
        for (int r = 0; r < 4; ++r) {
            const int c16 = (t & 3) + 4 * r;
            cp16(base + A32_OFF + buf * A32_BUF + aRow * A32_STRIDE + c16 * 16,
                 &A[(size_t)(m0 + aRow) * KD + kb + c16 * 4]);
        }
        cp_commit();
    };

    // convert A32[buf] -> A16[buf]; each thread converts its OWN staged bytes
    auto convertA = [&](int buf) {
        const uint32_t src = base + A32_OFF + buf * A32_BUF + aRow * A32_STRIDE;
        const uint32_t dst = base + A16_OFF + buf * A16_BUF;
#pragma unroll
        for (int r = 0; r < 4; ++r) {
            const int c16 = (t & 3) + 4 * r;
            float x, y, z, w;
            asm volatile("ld.shared.v4.f32 {%0,%1,%2,%3}, [%4];"
                         : "=f"(x), "=f"(y), "=f"(z), "=f"(w)
                         : "r"(src + c16 * 16));
            const uint32_t h0 = h2_pack(__float2half_rn(x), __float2half_rn(y));
            const uint32_t h1 = h2_pack(__float2half_rn(z), __float2half_rn(w));
            asm volatile("st.shared.v2.u32 [%0], {%1,%2};"
                         :: "r"(dst + SWZ(aRow * 128 + c16 * 8)), "r"(h0), "r"(h1));
        }
    };

    auto load_frags = [&](int cur, int st, uint32_t fa[2][4], uint32_t fb[2][4]) {
        const uint32_t aB = base + A16_OFF + cur * A16_BUF;
        const uint32_t bB = base + B16_OFF + cur * B16_BUF;
        const uint32_t k2 = st * 32;
#pragma unroll
        for (int mf = 0; mf < 2; ++mf)
            ldsm4(fa[mf], aB + aRowOff[mf] + ((aK + k2) ^ aXor[mf]));
#pragma unroll
        for (int q = 0; q < 2; ++q)
            ldsm4(fb[q], bB + bRowOff[q] + ((bK + k2) ^ bXor[q]));
    };

    auto do_mma = [&](uint32_t fa[2][4], uint32_t fb[2][4]) {
#pragma unroll
        for (int mf = 0; mf < 2; ++mf)
#pragma unroll
            for (int q = 0; q < 2; ++q)
#pragma unroll
                for (int h = 0; h < 2; ++h)
                    mma16816(c[mf][2 * q + h], fa[mf], &fb[q][2 * h]);
    };

    // ================== prologue: tiles 0 and 1 in flight =================
    stage(0, 0);
    stage(1, 1);
    cp_waitg<1>();         // tile 0 landed (tile 1 still flying)
    convertA(0);           // own bytes — no barrier needed
    __syncthreads();       // publish A16[0] + B16[0]

    uint32_t fa[2][2][4], fb[2][2][4];
    int buf = 0;           // buffer holding tile kt (ready)

    // ================== main loop ==============================
    // invariant at top of iter kt: buf holds tile kt (converted, published);
    // tile kt+1 staged (group possibly in flight); buffers rotate mod 3.
    for (int kt = 0; kt < TILES; ++kt) {
        const int nb1 = (buf + 1) % 3;       // will hold tile kt+1
        const int nb2 = (buf + 2) % 3;       // will hold tile kt+2
        const bool have1 = (kt + 1) < TILES;
        const bool have2 = (kt + 2) < TILES;

        if (have2) stage(nb2, kt + 2);

        load_frags(buf, 0, fa[0], fb[0]);
#pragma unroll
        for (int st = 0; st < 4; ++st) {
            if (st < 3) load_frags(buf, st + 1, fa[(st + 1) & 1], fb[(st + 1) & 1]);
            do_mma(fa[st & 1], fb[st & 1]);
        }

        if (have1) {
            if (have2) cp_waitg<1>(); else cp_waitg<0>();  // tile kt+1 landed
            convertA(nb1);                                 // own bytes
            __syncthreads();                               // publish for kt+1
        }
        buf = nb1;
    }

    // ---- store this split's partial (coalesced) ----
    float* __restrict__ part = g_part[blockIdx.y];
    const int cRow = (l >> 2);
    const int cCol = (l & 3) * 2;
#pragma unroll
    for (int mf = 0; mf < 2; ++mf) {
        const int rbase = m0 + warpM * 32 + mf * 16 + cRow;
#pragma unroll
        for (int nf = 0; nf < 4; ++nf) {
            const int col = warpN * 32 + nf * 8 + cCol;
            float2 v0; v0.x = c[mf][nf][0]; v0.y = c[mf][nf][1];
            float2 v1; v1.x = c[mf][nf][2]; v1.y = c[mf][nf][3];
            *reinterpret_cast<float2*>(&part[(size_t)rbase * FEA + col])       = v0;
            *reinterpret_cast<float2*>(&part[(size_t)(rbase + 8) * FEA + col]) = v1;
        }
    }

    // ---- inline reduction: last CTA per M-tile sums partials + bias ----
    __threadfence();
    __shared__ unsigned int tick;
    if (t == 0) tick = atomicAdd(&g_cnt[blockIdx.x], 1u);
    __syncthreads();
    if (tick == SPLITS - 1) {
        const float4* __restrict__ b4 = reinterpret_cast<const float4*>(bias);
        float4* __restrict__ o4 = reinterpret_cast<float4*>(out);
        for (int i = t; i < 128 * (FEA / 4); i += 512) {
            const int row = m0 + (i >> 5);
            const int c4  = i & 31;
            const size_t idx = (size_t)row * (FEA / 4) + c4;
            float4 o = b4[c4];
#pragma unroll
            for (int s = 0; s < SPLITS; ++s) {
                const float4 p = reinterpret_cast<const float4*>(g_part[s])[idx];
                o.x += p.x; o.y += p.y; o.z += p.z; o.w += p.w;
            }
            o4[idx] = o;
        }
        if (t == 0) g_cnt[blockIdx.x] = 0;   // reset for graph replay
    }
}

extern "C" void kernel_launch(void* const* d_in, const int* in_sizes, int n_in,
                              void* d_out, int out_size)
{
    const float* input = (const float*)d_in[0];  // [4096, 128]
    const float* adj   = (const float*)d_in[1];  // [4096, 4096]
    const float* rel   = (const float*)d_in[2];  // [4096, 128, 128]
    const float* W     = (const float*)d_in[3];  // [4096, 128, 128]
    const float* bias  = (const float*)d_in[4];  // [128]
    float* out = (float*)d_out;                  // [4096, 128]

    cudaFuncSetAttribute(hmma_gemm_kernel,
                         cudaFuncAttributeMaxDynamicSharedMemorySize, SMEM_REQ);

    node_transform_kernel<<<N_NODES, 128>>>(input, rel, W);
    hmma_gemm_kernel<<<dim3(32, SPLITS), 512, SMEM_REQ>>>(adj, bias, out);
}